// round 8
// baseline (speedup 1.0000x reference)
#include <cuda_runtime.h>

// CapsNet dynamic routing, fused, f32x2 over OD, o-dimension split across
// two lane-halves (5 output caps per thread) to cut register state and lift
// occupancy. b_t = u * Vsum so u (189 MB) is never materialized.

namespace {
constexpr int B_  = 256;
constexpr int IC_ = 1152;
constexpr int ID_ = 8;
constexpr int OC_ = 10;
constexpr int OH  = OC_ / 2;          // 5 o's per thread
constexpr int OD_ = 16;
constexpr int SOD = B_ * OC_ * OD_;   // 40960, layout [b][o][d]

constexpr int IBLK = 8;               // i's per smem chunk
constexpr int NCHK = 4;               // chunks per CTA (32 i total)
constexpr int BCH  = 16;              // batches per CTA
constexpr int NT   = 256;             // 8 dp-warps x (2 oh x 16 b) lanes
constexpr int GX   = IC_ / (IBLK * NCHK);  // 36
constexpr int GY   = B_ / BCH;             // 16

constexpr int W_TILE_F = IBLK * OC_ * OD_ * ID_;  // 10240 floats (40 KB)
constexpr int X_TILE_E = IBLK * 4 * BCH;          // 512 ulonglong2 (8 KB)
constexpr int SMEMB    = W_TILE_F * 4 + X_TILE_E * 16;  // 49152 B
constexpr int WT_ELEMS = IC_ * OC_ * OD_ * ID_;   // 1474560
constexpr float L2E = 1.4426950408889634f;
}

typedef unsigned long long ull;

__device__ __align__(16) float g_Wt[WT_ELEMS];  // [i][o][dp][k][dl]
__device__ __align__(16) float g_s[3][SOD];     // [b][o][d]
__device__ __align__(16) float g_Vsum[SOD];
__device__ __align__(16) float g_Vs[SOD];       // Vsum * log2(e)

__device__ __forceinline__ float fast_ex2(float x) {
    float y; asm("ex2.approx.ftz.f32 %0, %1;" : "=f"(y) : "f"(x)); return y;
}
__device__ __forceinline__ float fast_rcp(float x) {
    float y; asm("rcp.approx.ftz.f32 %0, %1;" : "=f"(y) : "f"(x)); return y;
}
__device__ __forceinline__ float fast_rsqrt(float x) {
    float y; asm("rsqrt.approx.ftz.f32 %0, %1;" : "=f"(y) : "f"(x)); return y;
}
__device__ __forceinline__ ull pack2(float lo, float hi) {
    ull r; asm("mov.b64 %0, {%1, %2};" : "=l"(r) : "f"(lo), "f"(hi)); return r;
}
__device__ __forceinline__ void unpack2(ull v, float& lo, float& hi) {
    asm("mov.b64 {%0, %1}, %2;" : "=f"(lo), "=f"(hi) : "l"(v));
}
__device__ __forceinline__ ull fma2(ull a, ull b, ull c) {
    ull d; asm("fma.rn.f32x2 %0, %1, %2, %3;" : "=l"(d) : "l"(a), "l"(b), "l"(c)); return d;
}
__device__ __forceinline__ ull mul2(ull a, ull b) {
    ull d; asm("mul.rn.f32x2 %0, %1, %2;" : "=l"(d) : "l"(a), "l"(b)); return d;
}
__device__ __forceinline__ ull add2(ull a, ull b) {
    ull d; asm("add.rn.f32x2 %0, %1, %2;" : "=l"(d) : "l"(a), "l"(b)); return d;
}

// Transpose W[i][o][d][k] -> g_Wt[i][o][dp][k][dl], zero accumulators.
__global__ void prepack_zero_kernel(const float* __restrict__ W) {
    int e = blockIdx.x * 512 + threadIdx.x;
    if (e < SOD) {
        g_s[0][e] = 0.f; g_s[1][e] = 0.f; g_s[2][e] = 0.f;
        g_Vsum[e] = 0.f;
    }
    if (e < WT_ELEMS) {
        int io = e >> 7;          // 128 floats per (i,o)
        int r  = e & 127;
        int dp = r >> 4;
        int k  = (r >> 1) & 7;
        int dl = r & 1;
        g_Wt[e] = W[(io * OD_ + 2 * dp + dl) * ID_ + k];
    }
}

// Routing pass. Grid (36, 16), block 256 = 8 dp-warps; lane = oh*16 + bl.
// Each thread: 5 output caps (o = oh*5+j), d-pair 2dp..2dp+1, one batch.
// Softmax Z combined across oh-halves with one 64-bit shfl_xor(16).
template<bool FIRST>
__global__ __launch_bounds__(NT, 3) void route_kernel(
    const float* __restrict__ x,   // [B, IC, ID]
    int which)
{
    extern __shared__ float sm[];
    float* Wsm = sm;                                            // 40 KB
    ulonglong2* XD = reinterpret_cast<ulonglong2*>(sm + W_TILE_F);  // 8 KB

    const int t    = threadIdx.x;
    const int dp   = t >> 5;        // warp id = d-pair, 0..7
    const int lane = t & 31;
    const int oh   = lane >> 4;     // 0..1
    const int bl   = lane & 15;     // 0..15
    const int obase = oh * OH;      // 0 or 5
    const int b    = blockIdx.y * BCH + bl;

    // loop-invariant softmax logit scales (Vsum*log2e) for this thread's o's
    ull Vp[OH];
    if (!FIRST) {
#pragma unroll
        for (int j = 0; j < OH; j++)
            Vp[j] = *reinterpret_cast<const ull*>(
                g_Vs + (((size_t)b * OC_ + obase + j) * OD_ + 2 * dp));
    }

    ull s[OH];
    const ull zz = pack2(0.f, 0.f);
#pragma unroll
    for (int j = 0; j < OH; j++) s[j] = zz;

    for (int c = 0; c < NCHK; c++) {
        const int i0 = blockIdx.x * (IBLK * NCHK) + c * IBLK;
        if (c) __syncthreads();     // drain readers of previous tiles

        // ---- W tile: straight copy of pre-transposed weights ----
        {
            const float4* src = reinterpret_cast<const float4*>(
                g_Wt + (size_t)i0 * (OC_ * OD_ * ID_));
            float4* dst = reinterpret_cast<float4*>(Wsm);
#pragma unroll
            for (int r = 0; r < W_TILE_F / 4 / NT; r++)   // 10
                dst[t + r * NT] = src[t + r * NT];
        }
        // ---- x tile: duplicated f32x2 pairs, layout [i][kp][bl] ----
        {
#pragma unroll
            for (int r = 0; r < 2; r++) {
                int e   = t + r * NT;      // 0..511
                int ikp = e >> 4;          // 0..31
                int bb  = e & 15;
                int i   = ikp >> 2;
                int kp  = ikp & 3;
                float2 v = *reinterpret_cast<const float2*>(
                    x + ((size_t)(blockIdx.y * BCH + bb) * IC_ + i0 + i) * ID_
                      + kp * 2);
                ulonglong2 w;
                w.x = pack2(v.x, v.x);
                w.y = pack2(v.y, v.y);
                XD[ikp * BCH + bb] = w;
            }
        }
        __syncthreads();

        const ulonglong2* W2 = reinterpret_cast<const ulonglong2*>(Wsm);

#pragma unroll 4
        for (int i = 0; i < IBLK; i++) {
            ulonglong2 x0 = XD[(i * 4 + 0) * BCH + bl];
            ulonglong2 x1 = XD[(i * 4 + 1) * BCH + bl];
            ulonglong2 x2 = XD[(i * 4 + 2) * BCH + bl];
            ulonglong2 x3 = XD[(i * 4 + 3) * BCH + bl];

            ull u[OH];
#pragma unroll
            for (int j = 0; j < OH; j++) {
                int wb = ((i * OC_ + obase + j) * ID_ + dp) * 4;
                ulonglong2 w01 = W2[wb];
                ulonglong2 w23 = W2[wb + 1];
                ulonglong2 w45 = W2[wb + 2];
                ulonglong2 w67 = W2[wb + 3];
                ull acc = mul2(w01.x, x0.x);
                acc = fma2(w01.y, x0.y, acc);
                acc = fma2(w23.x, x1.x, acc);
                acc = fma2(w23.y, x1.y, acc);
                acc = fma2(w45.x, x2.x, acc);
                acc = fma2(w45.y, x2.y, acc);
                acc = fma2(w67.x, x3.x, acc);
                acc = fma2(w67.y, x3.y, acc);
                u[j] = acc;
            }

            if (FIRST) {
#pragma unroll
                for (int j = 0; j < OH; j++) s[j] = add2(s[j], u[j]);
            } else {
                ull Zh = zz;
#pragma unroll
                for (int j = 0; j < OH; j++) {
                    ull lg = mul2(u[j], Vp[j]);
                    float l0, l1; unpack2(lg, l0, l1);
                    ull ep = pack2(fast_ex2(l0), fast_ex2(l1));
                    Zh = add2(Zh, ep);
                    u[j] = mul2(u[j], ep);      // u now holds u*e
                }
                // combine Z across the two oh-halves (partner lane^16)
                ull Zo = __shfl_xor_sync(0xffffffffu, Zh, 16);
                ull Z2 = add2(Zh, Zo);
                float Z0, Z1; unpack2(Z2, Z0, Z1);
                ull rp = pack2(fast_rcp(Z0), fast_rcp(Z1));
#pragma unroll
                for (int j = 0; j < OH; j++) s[j] = fma2(u[j], rp, s[j]);
            }
        }
    }

    // accumulate partial s into global [b][o][d]
    float* sp = g_s[which] + ((size_t)b * OC_ + obase) * OD_ + 2 * dp;
#pragma unroll
    for (int j = 0; j < OH; j++) {
        float a0, a1; unpack2(s[j], a0, a1);
        if (FIRST) { a0 *= (1.0f / OC_); a1 *= (1.0f / OC_); }
        atomicAdd(sp + j * OD_, a0);
        atomicAdd(sp + j * OD_ + 1, a1);
    }
}

// squash(s) per (b,o) over d; update Vsum / Vs, or write final output.
__global__ void squash_kernel(int which, float* __restrict__ out, int final_) {
    const float* __restrict__ s = g_s[which];
    int t  = blockIdx.x * 256 + threadIdx.x;   // SOD threads exactly
    int d  = t & 15;
    int bo = t >> 4;
    int idx = bo * OD_ + d;                    // [b][o][d]

    float sv = s[idx];
    float l2 = sv * sv;
#pragma unroll
    for (int off = 8; off > 0; off >>= 1)
        l2 += __shfl_xor_sync(0xffffffffu, l2, off);

    float coef = l2 * fast_rsqrt(l2) * fast_rcp(1.f + l2);
    float v = sv * coef;

    if (final_) {
        out[idx] = v;                           // output [B, OC, OD]
    } else {
        float nv = g_Vsum[idx] + v;
        g_Vsum[idx] = nv;
        g_Vs[idx] = nv * L2E;                   // * log2(e)
    }
}

extern "C" void kernel_launch(void* const* d_in, const int* in_sizes, int n_in,
                              void* d_out, int out_size) {
    const float* x = (const float*)d_in[0];   // [256,1152,8]
    const float* W = (const float*)d_in[1];   // [1152,10,16,8]
    float* out = (float*)d_out;               // [256,10,16]

    cudaFuncSetAttribute(route_kernel<true>,
                         cudaFuncAttributeMaxDynamicSharedMemorySize, SMEMB);
    cudaFuncSetAttribute(route_kernel<false>,
                         cudaFuncAttributeMaxDynamicSharedMemorySize, SMEMB);

    dim3 rg(GX, GY);
    int sgrid = SOD / 256;   // 160

    prepack_zero_kernel<<<(WT_ELEMS + 511) / 512, 512>>>(W);

    route_kernel<true><<<rg, NT, SMEMB>>>(x, 0);
    squash_kernel<<<sgrid, 256>>>(0, out, 0);

    route_kernel<false><<<rg, NT, SMEMB>>>(x, 1);
    squash_kernel<<<sgrid, 256>>>(1, out, 0);

    route_kernel<false><<<rg, NT, SMEMB>>>(x, 2);
    squash_kernel<<<sgrid, 256>>>(2, out, 1);
}